// round 2
// baseline (speedup 1.0000x reference)
#include <cuda_runtime.h>
#include <cuda_bf16.h>

#define BB 4
#define C 128
#define CO 256
#define H 128
#define W 128
#define HP 130
#define WP 130
#define NPT 9
#define KTOT (C*NPT)   // 1152

// -------- device scratch (static allocation only, per harness rules) --------
__device__ float g_xpad[BB*C*HP*WP];      // 34.6 MB padded input
__device__ float g_off[BB*H*W*2*NPT];     // offsets [b][h][w][18]
__device__ float g_wT[KTOT*CO];           // w_conv transposed: [k = c*9+n][o]
__device__ float g_stats[2*CO];           // per-channel scale, shift

// ---------------------------------------------------------------------------
__global__ void pad_kernel(const float* __restrict__ x) {
    int idx = blockIdx.x*blockDim.x + threadIdx.x;
    if (idx >= BB*C*HP*WP) return;
    int j = idx % WP; int t = idx / WP; int i = t % HP; int bc = t / HP;
    float v = 0.f;
    if (i >= 1 && i <= H && j >= 1 && j <= W)
        v = x[(bc*H + (i-1))*W + (j-1)];
    g_xpad[idx] = v;
}

__global__ void transpose_w(const float* __restrict__ w) {
    int idx = blockIdx.x*blockDim.x + threadIdx.x;
    if (idx >= CO*KTOT) return;
    int o = idx / KTOT, k = idx % KTOT;
    g_wT[k*CO + o] = w[idx];
}

// ---------------------------------------------------------------------------
// Offset conv: 18 output channels, 3x3, pad 1. One thread per (b,h,w).
__global__ __launch_bounds__(128) void offconv_kernel(
        const float* __restrict__ pw, const float* __restrict__ pb) {
    __shared__ float s_pw[576*20];           // [k_local][18] padded to 20
    int b = blockIdx.x / H, h = blockIdx.x % H;
    int w = threadIdx.x;
    float acc[18];
    #pragma unroll
    for (int j = 0; j < 18; j++) acc[j] = pb[j];

    for (int cc = 0; cc < 2; cc++) {
        __syncthreads();
        for (int i = threadIdx.x; i < 576*18; i += 128) {
            int k = i / 18, j = i - (i/18)*18;
            s_pw[k*20 + j] = pw[j*KTOT + cc*576 + k];
        }
        __syncthreads();
        for (int k = 0; k < 576; k++) {
            int c = cc*64 + k/9;
            int kidx = k - (k/9)*9;
            float xv = g_xpad[((b*C + c)*HP + h + kidx/3)*WP + w + kidx%3];
            const float4* r = (const float4*)(s_pw + k*20);
            float4 a0 = r[0], a1 = r[1], a2 = r[2], a3 = r[3];
            float b0 = s_pw[k*20+16], b1 = s_pw[k*20+17];
            acc[0]  += xv*a0.x; acc[1]  += xv*a0.y; acc[2]  += xv*a0.z; acc[3]  += xv*a0.w;
            acc[4]  += xv*a1.x; acc[5]  += xv*a1.y; acc[6]  += xv*a1.z; acc[7]  += xv*a1.w;
            acc[8]  += xv*a2.x; acc[9]  += xv*a2.y; acc[10] += xv*a2.z; acc[11] += xv*a2.w;
            acc[12] += xv*a3.x; acc[13] += xv*a3.y; acc[14] += xv*a3.z; acc[15] += xv*a3.w;
            acc[16] += xv*b0;   acc[17] += xv*b1;
        }
    }
    float* op = g_off + (((b*H + h)*W) + w)*18;
    #pragma unroll
    for (int j = 0; j < 18; j++) op[j] = acc[j];
}

// ---------------------------------------------------------------------------
// Fused bilinear gather + implicit GEMM.
// Block: one (b, h, 32-wide w tile). 256 threads = 256 output channels.
__global__ __launch_bounds__(256) void deform_main(float* __restrict__ out) {
    __shared__ float s_xoff[288*32];   // [cn = c_local*9+n][p] — also reused for epilogue
    __shared__ int4  s_ix[288];        // x0*WP, x1*WP, y0, y1 per (p,n), idx p*9+n
    __shared__ float4 s_g[288];        // g_lt, g_rb, g_lb, g_rt

    int b   = blockIdx.y;
    int tile = blockIdx.x;
    int h   = tile >> 2;
    int w0  = (tile & 3) << 5;
    int tid = threadIdx.x;

    // ---- phase 0: sampling params for 32 positions x 9 taps ----
    for (int i = tid; i < 288; i += 256) {
        int p = i / 9, n = i - (i/9)*9;
        int w = w0 + p;
        const float* offp = g_off + (((b*H + h)*W) + w)*18;
        float ox = offp[n], oy = offp[9+n];
        float px = (float)(h + n/3) + ox;   // h+1 + (n/3 - 1) + ox
        float py = (float)(w + n%3) + oy;
        float fx = floorf(px), fy = floorf(py);
        float x0 = fminf(fmaxf(fx,      0.f), 129.f);
        float x1 = fminf(fmaxf(fx+1.f,  0.f), 129.f);
        float y0 = fminf(fmaxf(fy,      0.f), 129.f);
        float y1 = fminf(fmaxf(fy+1.f,  0.f), 129.f);
        float pcx = fminf(fmaxf(px, 0.f), 129.f);
        float pcy = fminf(fmaxf(py, 0.f), 129.f);
        float wx0 = 1.f + (x0 - pcx), wx1 = 1.f - (x1 - pcx);
        float wy0 = 1.f + (y0 - pcy), wy1 = 1.f - (y1 - pcy);
        s_ix[i] = make_int4(((int)x0)*WP, ((int)x1)*WP, (int)y0, (int)y1);
        s_g[i]  = make_float4(wx0*wy0, wx1*wy1, wx0*wy1, wx1*wy0);
    }

    float acc[32];
    #pragma unroll
    for (int p = 0; p < 32; p++) acc[p] = 0.f;

    for (int cc = 0; cc < 4; cc++) {
        __syncthreads();   // params ready (cc=0) / previous GEMM done reading s_xoff
        // ---- phase A: gather 32 channels x 9 taps x 32 positions ----
        for (int i = tid; i < 288*32; i += 256) {
            int cn = i >> 5, p = i & 31;          // warp lanes -> consecutive p
            int c_local = cn / 9;
            int n = cn - c_local*9;
            int c = cc*32 + c_local;
            int pi = p*9 + n;
            const float* Xp = g_xpad + (size_t)(b*C + c)*(HP*WP);
            int4  q = s_ix[pi];
            float4 g = s_g[pi];
            float v = g.x * Xp[q.x + q.z] + g.y * Xp[q.y + q.w]
                    + g.z * Xp[q.x + q.w] + g.w * Xp[q.y + q.z];
            s_xoff[cn*32 + p] = v;
        }
        __syncthreads();
        // ---- phase B: GEMM slice, thread owns output channel o = tid ----
        const float* wT = g_wT + cc*288*CO;
        #pragma unroll 2
        for (int k = 0; k < 288; k++) {
            float wv = wT[k*CO + tid];            // coalesced
            const float4* xr = (const float4*)(s_xoff + k*32);
            #pragma unroll
            for (int p4 = 0; p4 < 8; p4++) {
                float4 xv = xr[p4];               // smem broadcast
                acc[p4*4+0] += wv*xv.x;
                acc[p4*4+1] += wv*xv.y;
                acc[p4*4+2] += wv*xv.z;
                acc[p4*4+3] += wv*xv.w;
            }
        }
    }

    // ---- epilogue: transpose through smem for coalesced stores ----
    __syncthreads();
    #pragma unroll
    for (int p = 0; p < 32; p++) s_xoff[tid*33 + p] = acc[p];  // stride-33: no bank conflict
    __syncthreads();
    for (int i = tid; i < CO*32; i += 256) {
        int o = i >> 5, p = i & 31;
        out[((b*CO + o)*H + h)*W + w0 + p] = s_xoff[o*33 + p];
    }
}

// ---------------------------------------------------------------------------
__global__ void bn_reduce(const float* __restrict__ out,
                          const float* __restrict__ gamma,
                          const float* __restrict__ beta) {
    int o = blockIdx.x;
    int tid = threadIdx.x;
    float s = 0.f, s2 = 0.f;
    for (int b = 0; b < BB; b++) {
        const float* p = out + (size_t)(b*CO + o)*(H*W);
        for (int i = tid; i < H*W; i += 256) {
            float v = p[i]; s += v; s2 += v*v;
        }
    }
    __shared__ float rs[256], rs2[256];
    rs[tid] = s; rs2[tid] = s2;
    __syncthreads();
    for (int st = 128; st > 0; st >>= 1) {
        if (tid < st) { rs[tid] += rs[tid+st]; rs2[tid] += rs2[tid+st]; }
        __syncthreads();
    }
    if (tid == 0) {
        const float inv = 1.f / (float)(BB*H*W);
        float mean = rs[0] * inv;
        float var  = rs2[0] * inv - mean*mean;
        float rstd = rsqrtf(var + 1e-5f);
        float sc = gamma[o] * rstd;
        g_stats[o]      = sc;
        g_stats[CO + o] = beta[o] - mean*sc;
    }
}

__global__ void bn_apply(float* __restrict__ out) {
    int idx = blockIdx.x*blockDim.x + threadIdx.x;
    const int total4 = BB*CO*H*W/4;
    if (idx >= total4) return;
    int o = ((idx*4) / (H*W)) % CO;
    float sc = g_stats[o], sh = g_stats[CO + o];
    float4 v = ((float4*)out)[idx];
    v.x = v.x*sc + sh; v.x = v.x >= 0.f ? v.x : 0.1f*v.x;
    v.y = v.y*sc + sh; v.y = v.y >= 0.f ? v.y : 0.1f*v.y;
    v.z = v.z*sc + sh; v.z = v.z >= 0.f ? v.z : 0.1f*v.z;
    v.w = v.w*sc + sh; v.w = v.w >= 0.f ? v.w : 0.1f*v.w;
    ((float4*)out)[idx] = v;
}

// ---------------------------------------------------------------------------
extern "C" void kernel_launch(void* const* d_in, const int* in_sizes, int n_in,
                              void* d_out, int out_size) {
    const float* x      = (const float*)d_in[0];
    const float* p_w    = (const float*)d_in[1];
    const float* p_b    = (const float*)d_in[2];
    const float* w_conv = (const float*)d_in[3];
    const float* gamma  = (const float*)d_in[4];
    const float* beta   = (const float*)d_in[5];
    float* out = (float*)d_out;

    pad_kernel   <<<(BB*C*HP*WP + 255)/256, 256>>>(x);
    transpose_w  <<<(CO*KTOT + 255)/256, 256>>>(w_conv);
    offconv_kernel<<<BB*H, 128>>>(p_w, p_b);
    deform_main  <<<dim3(H*W/32, BB), 256>>>(out);
    bn_reduce    <<<CO, 256>>>(out, gamma, beta);
    bn_apply     <<<(BB*CO*H*W/4 + 255)/256, 256>>>(out);
}

// round 5
// speedup vs baseline: 1.7414x; 1.7414x over previous
#include <cuda_runtime.h>
#include <cuda_bf16.h>
#include <cstdint>

#define BB 4
#define C 128
#define CO 256
#define H 128
#define W 128
#define HP 130
#define WP 130
#define HPWP (HP*WP)
#define KTOT 1152        // C*9, tap-major: k = n*128 + c

// ---------------- device scratch (static only, per harness rules) ----------
__device__ float g_xpad[BB*C*HP*WP];                 // padded input
__device__ float g_off[BB*H*W*2*9];                  // offsets [b][h][w][18]
__device__ __nv_bfloat16 g_wBhi[CO*KTOT];            // weights hi, [o][n*128+c]
__device__ __nv_bfloat16 g_wBlo[CO*KTOT];            // weights lo
__device__ float g_stats[2*CO];

// ---------------------------------------------------------------------------
__device__ __forceinline__ void mma_bf16(float* d, const uint32_t* a, const uint32_t* b) {
    asm volatile("mma.sync.aligned.m16n8k16.row.col.f32.bf16.bf16.f32 "
        "{%0,%1,%2,%3}, {%4,%5,%6,%7}, {%8,%9}, {%0,%1,%2,%3};"
        : "+f"(d[0]), "+f"(d[1]), "+f"(d[2]), "+f"(d[3])
        : "r"(a[0]), "r"(a[1]), "r"(a[2]), "r"(a[3]), "r"(b[0]), "r"(b[1]));
}

// ---------------------------------------------------------------------------
__global__ void pad_kernel(const float* __restrict__ x) {
    int idx = blockIdx.x*blockDim.x + threadIdx.x;
    if (idx >= BB*C*HP*WP) return;
    int j = idx % WP; int t = idx / WP; int i = t % HP; int bc = t / HP;
    float v = 0.f;
    if (i >= 1 && i <= H && j >= 1 && j <= W)
        v = x[(bc*H + (i-1))*W + (j-1)];
    g_xpad[idx] = v;
}

// split weights to bf16 hi/lo, reorder to tap-major k = n*128 + c
__global__ void wprep_kernel(const float* __restrict__ w) {
    int idx = blockIdx.x*blockDim.x + threadIdx.x;
    if (idx >= CO*KTOT) return;
    int o = idx / KTOT, r = idx % KTOT;
    int n = r >> 7, c = r & 127;
    float v = w[(o*C + c)*9 + n];
    __nv_bfloat16 hi = __float2bfloat16(v);
    __nv_bfloat16 lo = __float2bfloat16(v - __bfloat162float(hi));
    g_wBhi[idx] = hi;
    g_wBlo[idx] = lo;
}

// ---------------------------------------------------------------------------
// Offset conv: 18 out channels, 3x3, pad 1. One thread per (b,h,w).
__global__ __launch_bounds__(128) void offconv_kernel(
        const float* __restrict__ pw, const float* __restrict__ pb) {
    __shared__ float s_pw[576*20];
    int b = blockIdx.x / H, h = blockIdx.x % H;
    int w = threadIdx.x;
    float acc[18];
    #pragma unroll
    for (int j = 0; j < 18; j++) acc[j] = pb[j];

    for (int cc = 0; cc < 2; cc++) {
        __syncthreads();
        for (int i = threadIdx.x; i < 576*18; i += 128) {
            int k = i / 18, j = i - (i/18)*18;
            s_pw[k*20 + j] = pw[j*KTOT + cc*576 + k];
        }
        __syncthreads();
        for (int k = 0; k < 576; k++) {
            int c = cc*64 + k/9;
            int kidx = k - (k/9)*9;
            float xv = g_xpad[((b*C + c)*HP + h + kidx/3)*WP + w + kidx%3];
            const float4* r = (const float4*)(s_pw + k*20);
            float4 a0 = r[0], a1 = r[1], a2 = r[2], a3 = r[3];
            float b0 = s_pw[k*20+16], b1 = s_pw[k*20+17];
            acc[0]  += xv*a0.x; acc[1]  += xv*a0.y; acc[2]  += xv*a0.z; acc[3]  += xv*a0.w;
            acc[4]  += xv*a1.x; acc[5]  += xv*a1.y; acc[6]  += xv*a1.z; acc[7]  += xv*a1.w;
            acc[8]  += xv*a2.x; acc[9]  += xv*a2.y; acc[10] += xv*a2.z; acc[11] += xv*a2.w;
            acc[12] += xv*a3.x; acc[13] += xv*a3.y; acc[14] += xv*a3.z; acc[15] += xv*a3.w;
            acc[16] += xv*b0;   acc[17] += xv*b1;
        }
    }
    float* op = g_off + (((b*H + h)*W) + w)*18;
    #pragma unroll
    for (int j = 0; j < 18; j++) op[j] = acc[j];
}

// ---------------------------------------------------------------------------
// Deformable implicit GEMM via mma.sync m16n8k16 bf16 (hi/lo split, 3 products).
// CTA: 512 threads. Tile M=128 positions (one b,h row) x N=256 channels, K=1152.
// Warp grid 4m x 4n: each warp 32 pos x 64 ch.
// smem: A[128 rows x 40 bf16] hi/lo, B[256 rows x 40 bf16] hi/lo (row = 80B = 20 banks).
#define ROWB 80          // bytes per smem row (40 bf16)
#define OFF_AH 0
#define OFF_AL 10240
#define OFF_BH 20480
#define OFF_BL 40960
#define SMEM_DYN 61440

__global__ __launch_bounds__(512, 1) void deform_mma(float* __restrict__ out) {
    extern __shared__ char sm[];
    char* pAh = sm + OFF_AH;
    char* pAl = sm + OFF_AL;
    char* pBh = sm + OFF_BH;
    char* pBl = sm + OFF_BL;

    const int tid  = threadIdx.x;
    const int lane = tid & 31;
    const int wid  = tid >> 5;
    const int wm   = wid & 3;        // pos group (32 each)
    const int wn   = wid >> 2;       // channel group (64 each)
    const int b    = blockIdx.y;
    const int h    = blockIdx.x;

    const int r  = lane >> 2;        // fragment row group 0..7
    const int tq = lane & 3;         // fragment k/col group 0..3

    // gather role: p = position (w coord), q = channel octet
    const int p = tid >> 2;
    const int q = tid & 3;

    float acc[2][8][4];
    #pragma unroll
    for (int mi = 0; mi < 2; mi++)
        #pragma unroll
        for (int nt = 0; nt < 8; nt++)
            #pragma unroll
            for (int j = 0; j < 4; j++) acc[mi][nt][j] = 0.f;

    int i00 = 0, i01 = 0, i10 = 0, i11 = 0;
    float gg0 = 0.f, gg1 = 0.f, gg2 = 0.f, gg3 = 0.f;

    for (int i = 0; i < 36; i++) {
        const int n  = i >> 2;
        const int c0 = (i & 3) << 5;

        // sampling params once per tap
        if ((i & 3) == 0) {
            const float* offp = g_off + ((size_t)((b*H + h)*W + p))*18;
            float ox = offp[n], oy = offp[9 + n];
            float px = (float)(h + n/3) + ox;
            float py = (float)(p + n%3) + oy;
            float fx = floorf(px), fy = floorf(py);
            float x0 = fminf(fmaxf(fx,     0.f), 129.f);
            float x1 = fminf(fmaxf(fx+1.f, 0.f), 129.f);
            float y0 = fminf(fmaxf(fy,     0.f), 129.f);
            float y1 = fminf(fmaxf(fy+1.f, 0.f), 129.f);
            float pcx = fminf(fmaxf(px, 0.f), 129.f);
            float pcy = fminf(fmaxf(py, 0.f), 129.f);
            float wx0 = 1.f + (x0 - pcx), wx1 = 1.f - (x1 - pcx);
            float wy0 = 1.f + (y0 - pcy), wy1 = 1.f - (y1 - pcy);
            int ix0 = (int)x0 * WP, ix1 = (int)x1 * WP;
            int iy0 = (int)y0,      iy1 = (int)y1;
            i00 = ix0 + iy0; i01 = ix0 + iy1; i10 = ix1 + iy0; i11 = ix1 + iy1;
            gg0 = wx0*wy0; gg1 = wx1*wy1; gg2 = wx0*wy1; gg3 = wx1*wy0;
        }

        // ---- B tile load: 256 rows x 32 bf16, hi & lo ----
        #pragma unroll
        for (int rep = 0; rep < 2; rep++) {
            int idx = tid + rep*512;
            int o = idx >> 2, j = idx & 3;
            const uint4* sh = (const uint4*)(g_wBhi + (size_t)o*KTOT + n*128 + c0) + j;
            const uint4* sl = (const uint4*)(g_wBlo + (size_t)o*KTOT + n*128 + c0) + j;
            *(uint4*)(pBh + o*ROWB + j*16) = *sh;
            *(uint4*)(pBl + o*ROWB + j*16) = *sl;
        }

        // ---- A gather: 8 channels for position p ----
        {
            const float* Xc = g_xpad + ((size_t)(b*C + c0 + q*8))*HPWP;
            #pragma unroll
            for (int kk = 0; kk < 8; kk += 2) {
                const float* X0 = Xc + (size_t)kk*HPWP;
                const float* X1 = X0 + HPWP;
                float v0 = gg0*X0[i00] + gg1*X0[i11] + gg2*X0[i01] + gg3*X0[i10];
                float v1 = gg0*X1[i00] + gg1*X1[i11] + gg2*X1[i01] + gg3*X1[i10];
                __nv_bfloat16 h0 = __float2bfloat16(v0);
                __nv_bfloat16 h1 = __float2bfloat16(v1);
                __nv_bfloat16 l0 = __float2bfloat16(v0 - __bfloat162float(h0));
                __nv_bfloat16 l1 = __float2bfloat16(v1 - __bfloat162float(h1));
                uint32_t hp = (uint32_t)*(unsigned short*)&h0 | ((uint32_t)*(unsigned short*)&h1 << 16);
                uint32_t lp = (uint32_t)*(unsigned short*)&l0 | ((uint32_t)*(unsigned short*)&l1 << 16);
                int byte = p*ROWB + (q*8 + kk)*2;
                *(uint32_t*)(pAh + byte) = hp;
                *(uint32_t*)(pAl + byte) = lp;
            }
        }

        __syncthreads();

        // ---- MMA phase ----
        #pragma unroll
        for (int ks = 0; ks < 2; ks++) {
            const int kb = ks*16;
            uint32_t ah[2][4], al[2][4];
            #pragma unroll
            for (int mi = 0; mi < 2; mi++) {
                int row = wm*32 + mi*16 + r;
                int base = row*ROWB + (kb + tq*2)*2;
                ah[mi][0] = *(const uint32_t*)(pAh + base);
                ah[mi][1] = *(const uint32_t*)(pAh + base + 8*ROWB);
                ah[mi][2] = *(const uint32_t*)(pAh + base + 16);
                ah[mi][3] = *(const uint32_t*)(pAh + base + 8*ROWB + 16);
                al[mi][0] = *(const uint32_t*)(pAl + base);
                al[mi][1] = *(const uint32_t*)(pAl + base + 8*ROWB);
                al[mi][2] = *(const uint32_t*)(pAl + base + 16);
                al[mi][3] = *(const uint32_t*)(pAl + base + 8*ROWB + 16);
            }
            #pragma unroll
            for (int nt = 0; nt < 8; nt++) {
                int nrow = wn*64 + nt*8 + r;
                int nb = nrow*ROWB + (kb + tq*2)*2;
                uint32_t bh[2], bl[2];
                bh[0] = *(const uint32_t*)(pBh + nb);
                bh[1] = *(const uint32_t*)(pBh + nb + 16);
                bl[0] = *(const uint32_t*)(pBl + nb);
                bl[1] = *(const uint32_t*)(pBl + nb + 16);
                #pragma unroll
                for (int mi = 0; mi < 2; mi++) {
                    mma_bf16(acc[mi][nt], ah[mi], bh);   // hi*hi
                    mma_bf16(acc[mi][nt], ah[mi], bl);   // hi*lo
                    mma_bf16(acc[mi][nt], al[mi], bh);   // lo*hi
                }
            }
        }
        __syncthreads();
    }

    // ---- epilogue: transpose via smem in 4 channel-quarters of 64 ----
    float* sepi = (float*)sm;        // [64 ch][129 pos] fp32 = 33 KB
    for (int qt = 0; qt < 4; qt++) {
        if (wn == qt) {
            #pragma unroll
            for (int mi = 0; mi < 2; mi++) {
                int pos0 = wm*32 + mi*16 + r;
                #pragma unroll
                for (int nt = 0; nt < 8; nt++) {
                    int ch0 = nt*8 + tq*2;
                    sepi[(ch0  )*129 + pos0    ] = acc[mi][nt][0];
                    sepi[(ch0+1)*129 + pos0    ] = acc[mi][nt][1];
                    sepi[(ch0  )*129 + pos0 + 8] = acc[mi][nt][2];
                    sepi[(ch0+1)*129 + pos0 + 8] = acc[mi][nt][3];
                }
            }
        }
        __syncthreads();
        {
            int ri = tid >> 3, j = tid & 7;          // 64 rows x 8 segs of 16
            int o = qt*64 + ri;
            const float* src = sepi + ri*129 + j*16;
            float* dst = out + (((size_t)b*CO + o)*H + h)*W + j*16;
            #pragma unroll
            for (int k4 = 0; k4 < 4; k4++) {
                float4 v = make_float4(src[k4*4+0], src[k4*4+1], src[k4*4+2], src[k4*4+3]);
                *(float4*)(dst + k4*4) = v;
            }
        }
        __syncthreads();
    }
}

// ---------------------------------------------------------------------------
__global__ void bn_reduce(const float* __restrict__ out,
                          const float* __restrict__ gamma,
                          const float* __restrict__ beta) {
    int o = blockIdx.x;
    int tid = threadIdx.x;
    float s = 0.f, s2 = 0.f;
    for (int b = 0; b < BB; b++) {
        const float* p = out + (size_t)(b*CO + o)*(H*W);
        for (int i = tid; i < H*W; i += 256) {
            float v = p[i]; s += v; s2 += v*v;
        }
    }
    __shared__ float rs[256], rs2[256];
    rs[tid] = s; rs2[tid] = s2;
    __syncthreads();
    for (int st = 128; st > 0; st >>= 1) {
        if (tid < st) { rs[tid] += rs[tid+st]; rs2[tid] += rs2[tid+st]; }
        __syncthreads();
    }
    if (tid == 0) {
        const float inv = 1.f / (float)(BB*H*W);
        float mean = rs[0] * inv;
        float var  = rs2[0] * inv - mean*mean;
        float rstd = rsqrtf(var + 1e-5f);
        float sc = gamma[o] * rstd;
        g_stats[o]      = sc;
        g_stats[CO + o] = beta[o] - mean*sc;
    }
}

__global__ void bn_apply(float* __restrict__ out) {
    int idx = blockIdx.x*blockDim.x + threadIdx.x;
    const int total4 = BB*CO*H*W/4;
    if (idx >= total4) return;
    int o = ((idx*4) / (H*W)) % CO;
    float sc = g_stats[o], sh = g_stats[CO + o];
    float4 v = ((float4*)out)[idx];
    v.x = v.x*sc + sh; v.x = v.x >= 0.f ? v.x : 0.1f*v.x;
    v.y = v.y*sc + sh; v.y = v.y >= 0.f ? v.y : 0.1f*v.y;
    v.z = v.z*sc + sh; v.z = v.z >= 0.f ? v.z : 0.1f*v.z;
    v.w = v.w*sc + sh; v.w = v.w >= 0.f ? v.w : 0.1f*v.w;
    ((float4*)out)[idx] = v;
}

// ---------------------------------------------------------------------------
extern "C" void kernel_launch(void* const* d_in, const int* in_sizes, int n_in,
                              void* d_out, int out_size) {
    const float* x      = (const float*)d_in[0];
    const float* p_w    = (const float*)d_in[1];
    const float* p_b    = (const float*)d_in[2];
    const float* w_conv = (const float*)d_in[3];
    const float* gamma  = (const float*)d_in[4];
    const float* beta   = (const float*)d_in[5];
    float* out = (float*)d_out;

    cudaFuncSetAttribute(deform_mma, cudaFuncAttributeMaxDynamicSharedMemorySize, SMEM_DYN);

    pad_kernel    <<<(BB*C*HP*WP + 255)/256, 256>>>(x);
    wprep_kernel  <<<(CO*KTOT + 255)/256, 256>>>(w_conv);
    offconv_kernel<<<BB*H, 128>>>(p_w, p_b);
    deform_mma    <<<dim3(H, BB), 512, SMEM_DYN>>>(out);
    bn_reduce     <<<CO, 256>>>(out, gamma, beta);
    bn_apply      <<<(BB*CO*H*W/4 + 255)/256, 256>>>(out);
}

// round 6
// speedup vs baseline: 2.1978x; 1.2621x over previous
#include <cuda_runtime.h>
#include <cuda_bf16.h>
#include <cstdint>

#define BB 4
#define C 128
#define CO 256
#define H 128
#define W 128
#define HP 130
#define WP 130
#define HPWP (HP*WP)
#define KTOT 1152        // C*9, tap-major: k = n*128 + c

// ---------------- device scratch (static only, per harness rules) ----------
__device__ float g_xpad[BB*C*HP*WP];                 // padded input
__device__ float g_off[BB*H*W*2*9];                  // offsets [b][h][w][18]
__device__ __nv_bfloat16 g_wBhi[CO*KTOT];            // weights hi, [o][n*128+c]
__device__ __nv_bfloat16 g_wBlo[CO*KTOT];            // weights lo
__device__ float g_stats[2*CO];

// ---------------- PTX helpers ----------------------------------------------
__device__ __forceinline__ uint32_t smem_u32(const void* p) {
    uint32_t a;
    asm("{ .reg .u64 t; cvta.to.shared.u64 t, %1; cvt.u32.u64 %0, t; }" : "=r"(a) : "l"(p));
    return a;
}
__device__ __forceinline__ void mma_bf16(float* d, const uint32_t* a, const uint32_t* b) {
    asm volatile("mma.sync.aligned.m16n8k16.row.col.f32.bf16.bf16.f32 "
        "{%0,%1,%2,%3}, {%4,%5,%6,%7}, {%8,%9}, {%0,%1,%2,%3};"
        : "+f"(d[0]), "+f"(d[1]), "+f"(d[2]), "+f"(d[3])
        : "r"(a[0]), "r"(a[1]), "r"(a[2]), "r"(a[3]), "r"(b[0]), "r"(b[1]));
}
__device__ __forceinline__ void ldsm4(uint32_t* r, uint32_t addr) {
    asm volatile("ldmatrix.sync.aligned.m8n8.x4.shared.b16 {%0,%1,%2,%3}, [%4];"
        : "=r"(r[0]), "=r"(r[1]), "=r"(r[2]), "=r"(r[3]) : "r"(addr));
}
__device__ __forceinline__ void cp16(uint32_t dst, const void* src) {
    asm volatile("cp.async.cg.shared.global [%0], [%1], 16;" :: "r"(dst), "l"(src));
}
#define CP_COMMIT() asm volatile("cp.async.commit_group;" ::: "memory")
#define CP_WAIT0()  asm volatile("cp.async.wait_group 0;" ::: "memory")

// ---------------------------------------------------------------------------
__global__ void pad_kernel(const float* __restrict__ x) {
    int idx = blockIdx.x*blockDim.x + threadIdx.x;
    if (idx >= BB*C*HP*WP) return;
    int j = idx % WP; int t = idx / WP; int i = t % HP; int bc = t / HP;
    float v = 0.f;
    if (i >= 1 && i <= H && j >= 1 && j <= W)
        v = x[(bc*H + (i-1))*W + (j-1)];
    g_xpad[idx] = v;
}

// split weights to bf16 hi/lo, reorder to tap-major k = n*128 + c
__global__ void wprep_kernel(const float* __restrict__ w) {
    int idx = blockIdx.x*blockDim.x + threadIdx.x;
    if (idx >= CO*KTOT) return;
    int o = idx / KTOT, r = idx % KTOT;
    int n = r >> 7, c = r & 127;
    float v = w[(o*C + c)*9 + n];
    __nv_bfloat16 hi = __float2bfloat16(v);
    __nv_bfloat16 lo = __float2bfloat16(v - __bfloat162float(hi));
    g_wBhi[idx] = hi;
    g_wBlo[idx] = lo;
}

// ---------------------------------------------------------------------------
// Offset conv: 18 out channels, 3x3, pad 1. One thread per (b,h,w).
__global__ __launch_bounds__(128) void offconv_kernel(
        const float* __restrict__ pw, const float* __restrict__ pb) {
    __shared__ float s_pw[576*20];
    int b = blockIdx.x / H, h = blockIdx.x % H;
    int w = threadIdx.x;
    float acc[18];
    #pragma unroll
    for (int j = 0; j < 18; j++) acc[j] = pb[j];

    for (int cc = 0; cc < 2; cc++) {
        __syncthreads();
        for (int i = threadIdx.x; i < 576*18; i += 128) {
            int k = i / 18, j = i - (i/18)*18;
            s_pw[k*20 + j] = pw[j*KTOT + cc*576 + k];
        }
        __syncthreads();
        for (int k = 0; k < 576; k++) {
            int c = cc*64 + k/9;
            int kidx = k - (k/9)*9;
            float xv = g_xpad[((b*C + c)*HP + h + kidx/3)*WP + w + kidx%3];
            const float4* r = (const float4*)(s_pw + k*20);
            float4 a0 = r[0], a1 = r[1], a2 = r[2], a3 = r[3];
            float b0 = s_pw[k*20+16], b1 = s_pw[k*20+17];
            acc[0]  += xv*a0.x; acc[1]  += xv*a0.y; acc[2]  += xv*a0.z; acc[3]  += xv*a0.w;
            acc[4]  += xv*a1.x; acc[5]  += xv*a1.y; acc[6]  += xv*a1.z; acc[7]  += xv*a1.w;
            acc[8]  += xv*a2.x; acc[9]  += xv*a2.y; acc[10] += xv*a2.z; acc[11] += xv*a2.w;
            acc[12] += xv*a3.x; acc[13] += xv*a3.y; acc[14] += xv*a3.z; acc[15] += xv*a3.w;
            acc[16] += xv*b0;   acc[17] += xv*b1;
        }
    }
    float* op = g_off + (((b*H + h)*W) + w)*18;
    #pragma unroll
    for (int j = 0; j < 18; j++) op[j] = acc[j];
}

// ---------------------------------------------------------------------------
// Deformable implicit GEMM, mma.sync m16n8k16 bf16 hi/lo split (3 products).
// CTA 512 thr, tile M=128 pos x N=256 ch, K=1152 in 72 half-chunks of k=16.
// Software pipeline: gather LDGs for hc+1 issued before MMA(hc).
// smem double-buffered; rows stride 48B (conflict-free ldmatrix).
#define NHC 72
#define ARS 48
#define S_AH 0
#define S_AL 6144
#define S_BH 12288
#define S_BL 24576
#define STG  36864
#define SMEM_DYN (2*STG)

__global__ __launch_bounds__(512, 1) void deform_mma(float* __restrict__ out) {
    extern __shared__ char sm[];
    const int tid  = threadIdx.x;
    const int lane = tid & 31;
    const int wid  = tid >> 5;
    const int wm   = wid & 3;        // pos group (32 each)
    const int wn   = wid >> 2;       // channel group (64 each)
    const int b    = blockIdx.y;
    const int h    = blockIdx.x;
    const int p    = tid >> 2;       // gather position
    const int q    = tid & 3;        // gather channel quartet
    const uint32_t sbase = smem_u32(sm);

    // ldmatrix lane byte-offsets (within Ah / Bh planes)
    const uint32_t aoff = (uint32_t)((wm*32 + (lane & 7) + ((lane >> 3) & 1)*8)*ARS + (lane >> 4)*16);
    const uint32_t boff = (uint32_t)((wn*64 + (lane & 7) + (lane >> 4)*8)*ARS + ((lane >> 3) & 1)*16);

    float acc[2][8][4];
    #pragma unroll
    for (int mi = 0; mi < 2; mi++)
        #pragma unroll
        for (int nt = 0; nt < 8; nt++)
            #pragma unroll
            for (int j = 0; j < 4; j++) acc[mi][nt][j] = 0.f;

    int i00 = 0, i01 = 0, i10 = 0, i11 = 0;
    float gg0 = 0.f, gg1 = 0.f, gg2 = 0.f, gg3 = 0.f;
    float raw[16];

    // ---- params for tap n (this thread's position) ----
    auto calc_params = [&](int n) {
        const float* offp = g_off + ((size_t)((b*H + h)*W + p))*18;
        float ox = offp[n], oy = offp[9 + n];
        float px = (float)(h + n/3) + ox;
        float py = (float)(p + n%3) + oy;
        float fx = floorf(px), fy = floorf(py);
        float x0 = fminf(fmaxf(fx,     0.f), 129.f);
        float x1 = fminf(fmaxf(fx+1.f, 0.f), 129.f);
        float y0 = fminf(fmaxf(fy,     0.f), 129.f);
        float y1 = fminf(fmaxf(fy+1.f, 0.f), 129.f);
        float pcx = fminf(fmaxf(px, 0.f), 129.f);
        float pcy = fminf(fmaxf(py, 0.f), 129.f);
        float wx0 = 1.f + (x0 - pcx), wx1 = 1.f - (x1 - pcx);
        float wy0 = 1.f + (y0 - pcy), wy1 = 1.f - (y1 - pcy);
        int ix0 = (int)x0 * WP, ix1 = (int)x1 * WP;
        int iy0 = (int)y0,      iy1 = (int)y1;
        i00 = ix0 + iy0; i01 = ix0 + iy1; i10 = ix1 + iy0; i11 = ix1 + iy1;
        gg0 = wx0*wy0; gg1 = wx1*wy1; gg2 = wx0*wy1; gg3 = wx1*wy0;
    };
    auto prefetch = [&](int hc2) {
        int ch = (hc2 & 7) * 16;
        const float* __restrict__ base = g_xpad + ((size_t)(b*C + ch + q*4))*HPWP;
        #pragma unroll
        for (int cc = 0; cc < 4; cc++) {
            const float* __restrict__ Xp = base + (size_t)cc*HPWP;
            raw[cc*4+0] = Xp[i00];
            raw[cc*4+1] = Xp[i11];
            raw[cc*4+2] = Xp[i01];
            raw[cc*4+3] = Xp[i10];
        }
    };

    calc_params(0);
    prefetch(0);

    for (int hc = 0; hc < NHC; hc++) {
        const int s = hc & 1;
        const uint32_t stu = sbase + s*STG;
        char* st = sm + s*STG;

        // ---- combine + convert + store A (values prefetched last iter) ----
        {
            uint32_t hp0, hp1, lp0, lp1;
            float v0 = gg0*raw[0]  + gg1*raw[1]  + gg2*raw[2]  + gg3*raw[3];
            float v1 = gg0*raw[4]  + gg1*raw[5]  + gg2*raw[6]  + gg3*raw[7];
            float v2 = gg0*raw[8]  + gg1*raw[9]  + gg2*raw[10] + gg3*raw[11];
            float v3 = gg0*raw[12] + gg1*raw[13] + gg2*raw[14] + gg3*raw[15];
            __nv_bfloat16 h0 = __float2bfloat16(v0), h1 = __float2bfloat16(v1);
            __nv_bfloat16 h2 = __float2bfloat16(v2), h3 = __float2bfloat16(v3);
            __nv_bfloat16 l0 = __float2bfloat16(v0 - __bfloat162float(h0));
            __nv_bfloat16 l1 = __float2bfloat16(v1 - __bfloat162float(h1));
            __nv_bfloat16 l2 = __float2bfloat16(v2 - __bfloat162float(h2));
            __nv_bfloat16 l3 = __float2bfloat16(v3 - __bfloat162float(h3));
            hp0 = (uint32_t)*(unsigned short*)&h0 | ((uint32_t)*(unsigned short*)&h1 << 16);
            hp1 = (uint32_t)*(unsigned short*)&h2 | ((uint32_t)*(unsigned short*)&h3 << 16);
            lp0 = (uint32_t)*(unsigned short*)&l0 | ((uint32_t)*(unsigned short*)&l1 << 16);
            lp1 = (uint32_t)*(unsigned short*)&l2 | ((uint32_t)*(unsigned short*)&l3 << 16);
            *(uint2*)(st + S_AH + p*ARS + q*8) = make_uint2(hp0, hp1);
            *(uint2*)(st + S_AL + p*ARS + q*8) = make_uint2(lp0, lp1);
        }

        // ---- B tile via cp.async (256 rows x 16 k, hi & lo) ----
        {
            int o = tid >> 1, seg = tid & 1;
            int n = hc >> 3, ch = (hc & 7)*16;
            size_t srcoff = (size_t)o*KTOT + n*128 + ch + seg*8;
            cp16(stu + S_BH + o*ARS + seg*16, g_wBhi + srcoff);
            cp16(stu + S_BL + o*ARS + seg*16, g_wBlo + srcoff);
            CP_COMMIT();
        }

        // ---- prefetch gather for hc+1 (hidden under MMA below) ----
        if (hc + 1 < NHC) {
            int hn = hc + 1;
            if ((hn & 7) == 0) calc_params(hn >> 3);
            prefetch(hn);
        }

        CP_WAIT0();
        __syncthreads();

        // ---- MMA on stage s ----
        uint32_t ah[2][4], al[2][4];
        ldsm4(ah[0], stu + S_AH + aoff);
        ldsm4(ah[1], stu + S_AH + aoff + 16*ARS);
        ldsm4(al[0], stu + S_AL + aoff);
        ldsm4(al[1], stu + S_AL + aoff + 16*ARS);
        #pragma unroll
        for (int j = 0; j < 4; j++) {
            uint32_t bh[4], bl[4];
            ldsm4(bh, stu + S_BH + boff + j*16*ARS);
            ldsm4(bl, stu + S_BL + boff + j*16*ARS);
            #pragma unroll
            for (int mi = 0; mi < 2; mi++) {
                mma_bf16(acc[mi][2*j],   ah[mi], bh);
                mma_bf16(acc[mi][2*j],   ah[mi], bl);
                mma_bf16(acc[mi][2*j],   al[mi], bh);
                mma_bf16(acc[mi][2*j+1], ah[mi], bh + 2);
                mma_bf16(acc[mi][2*j+1], ah[mi], bl + 2);
                mma_bf16(acc[mi][2*j+1], al[mi], bh + 2);
            }
        }
    }

    __syncthreads();

    // ---- epilogue: transpose via smem in 4 channel-quarters of 64 ----
    float* sepi = (float*)sm;        // [64 ch][129 pos] fp32 = 33 KB
    const int r  = lane >> 2;
    const int tq = lane & 3;
    for (int qt = 0; qt < 4; qt++) {
        if (wn == qt) {
            #pragma unroll
            for (int mi = 0; mi < 2; mi++) {
                int pos0 = wm*32 + mi*16 + r;
                #pragma unroll
                for (int nt = 0; nt < 8; nt++) {
                    int ch0 = nt*8 + tq*2;
                    sepi[(ch0  )*129 + pos0    ] = acc[mi][nt][0];
                    sepi[(ch0+1)*129 + pos0    ] = acc[mi][nt][1];
                    sepi[(ch0  )*129 + pos0 + 8] = acc[mi][nt][2];
                    sepi[(ch0+1)*129 + pos0 + 8] = acc[mi][nt][3];
                }
            }
        }
        __syncthreads();
        {
            int ri = tid >> 3, j = tid & 7;          // 64 rows x 8 segs of 16
            int o = qt*64 + ri;
            const float* src = sepi + ri*129 + j*16;
            float* dst = out + (((size_t)b*CO + o)*H + h)*W + j*16;
            #pragma unroll
            for (int k4 = 0; k4 < 4; k4++) {
                float4 v = make_float4(src[k4*4+0], src[k4*4+1], src[k4*4+2], src[k4*4+3]);
                *(float4*)(dst + k4*4) = v;
            }
        }
        __syncthreads();
    }
}

// ---------------------------------------------------------------------------
__global__ void bn_reduce(const float* __restrict__ out,
                          const float* __restrict__ gamma,
                          const float* __restrict__ beta) {
    int o = blockIdx.x;
    int tid = threadIdx.x;
    float s = 0.f, s2 = 0.f;
    for (int b = 0; b < BB; b++) {
        const float* p = out + (size_t)(b*CO + o)*(H*W);
        for (int i = tid; i < H*W; i += 256) {
            float v = p[i]; s += v; s2 += v*v;
        }
    }
    __shared__ float rs[256], rs2[256];
    rs[tid] = s; rs2[tid] = s2;
    __syncthreads();
    for (int st = 128; st > 0; st >>= 1) {
        if (tid < st) { rs[tid] += rs[tid+st]; rs2[tid] += rs2[tid+st]; }
        __syncthreads();
    }
    if (tid == 0) {
        const float inv = 1.f / (float)(BB*H*W);
        float mean = rs[0] * inv;
        float var  = rs2[0] * inv - mean*mean;
        float rstd = rsqrtf(var + 1e-5f);
        float sc = gamma[o] * rstd;
        g_stats[o]      = sc;
        g_stats[CO + o] = beta[o] - mean*sc;
    }
}

__global__ void bn_apply(float* __restrict__ out) {
    int idx = blockIdx.x*blockDim.x + threadIdx.x;
    const int total4 = BB*CO*H*W/4;
    if (idx >= total4) return;
    int o = ((idx*4) / (H*W)) % CO;
    float sc = g_stats[o], sh = g_stats[CO + o];
    float4 v = ((float4*)out)[idx];
    v.x = v.x*sc + sh; v.x = v.x >= 0.f ? v.x : 0.1f*v.x;
    v.y = v.y*sc + sh; v.y = v.y >= 0.f ? v.y : 0.1f*v.y;
    v.z = v.z*sc + sh; v.z = v.z >= 0.f ? v.z : 0.1f*v.z;
    v.w = v.w*sc + sh; v.w = v.w >= 0.f ? v.w : 0.1f*v.w;
    ((float4*)out)[idx] = v;
}

// ---------------------------------------------------------------------------
extern "C" void kernel_launch(void* const* d_in, const int* in_sizes, int n_in,
                              void* d_out, int out_size) {
    const float* x      = (const float*)d_in[0];
    const float* p_w    = (const float*)d_in[1];
    const float* p_b    = (const float*)d_in[2];
    const float* w_conv = (const float*)d_in[3];
    const float* gamma  = (const float*)d_in[4];
    const float* beta   = (const float*)d_in[5];
    float* out = (float*)d_out;

    cudaFuncSetAttribute(deform_mma, cudaFuncAttributeMaxDynamicSharedMemorySize, SMEM_DYN);

    pad_kernel    <<<(BB*C*HP*WP + 255)/256, 256>>>(x);
    wprep_kernel  <<<(CO*KTOT + 255)/256, 256>>>(w_conv);
    offconv_kernel<<<BB*H, 128>>>(p_w, p_b);
    deform_mma    <<<dim3(H, BB), 512, SMEM_DYN>>>(out);
    bn_reduce     <<<CO, 256>>>(out, gamma, beta);
    bn_apply      <<<(BB*CO*H*W/4 + 255)/256, 256>>>(out);
}